// round 11
// baseline (speedup 1.0000x reference)
#include <cuda_runtime.h>
#include <math.h>

#define BB 8
#define LL 8192
#define CCH 256
#define NN 512
#define KK 16
#define FMINF 1.17549435e-38f
#define NCAND 32

// scratch (no allocations allowed)
__device__ float g_w[BB * NN];            // FTZ proto_weights
__device__ float g_pn2[NN];               // |p_n|^2
__device__ float g_qq[BB * LL];           // |q_l|^2
__device__ float g_Pz[NN * CCH];          // element-transposed P (fragment-ready)
__device__ float g_Qz[BB * LL * CCH];     // element-transposed Q

__device__ __forceinline__ float warp_maxf(float v) {
    #pragma unroll
    for (int o = 16; o; o >>= 1) v = fmaxf(v, __shfl_xor_sync(0xffffffffu, v, o));
    return v;
}
__device__ __forceinline__ float warp_sumf(float v) {
    #pragma unroll
    for (int o = 16; o; o >>= 1) v += __shfl_xor_sync(0xffffffffu, v, o);
    return v;
}
__device__ __forceinline__ double warp_sumd(double v) {
    #pragma unroll
    for (int o = 16; o; o >>= 1) v += __shfl_xor_sync(0xffffffffu, v, o);
    return v;
}

__device__ __forceinline__ void mma_tf32(float& c0, float& c1, float& c2, float& c3,
                                         float a0, float a1, float a2, float a3,
                                         float b0, float b1) {
    asm volatile(
        "mma.sync.aligned.m16n8k8.row.col.f32.tf32.tf32.f32 "
        "{%0,%1,%2,%3}, {%4,%5,%6,%7}, {%8,%9}, {%0,%1,%2,%3};"
        : "+f"(c0), "+f"(c1), "+f"(c2), "+f"(c3)
        : "r"(__float_as_uint(a0)), "r"(__float_as_uint(a1)),
          "r"(__float_as_uint(a2)), "r"(__float_as_uint(a3)),
          "r"(__float_as_uint(b0)), "r"(__float_as_uint(b1)));
}

__device__ __forceinline__ float dot8(const float4& qa, const float4& qb,
                                      const float4& pa, const float4& pb) {
    float s = 0.f;
    s = fmaf(qa.x, pa.x, s); s = fmaf(qa.y, pa.y, s);
    s = fmaf(qa.z, pa.z, s); s = fmaf(qa.w, pa.w, s);
    s = fmaf(qb.x, pb.x, s); s = fmaf(qb.y, pb.y, s);
    s = fmaf(qb.z, pb.z, s); s = fmaf(qb.w, pb.w, s);
    return s;
}

// ---------------------------------------------------------------------------
// prep: per-batch FTZ proto weights
// ---------------------------------------------------------------------------
__global__ void prep_w_kernel(const float* __restrict__ P,
                              const float* __restrict__ gt) {
    int b = blockIdx.x;
    int tid = threadIdx.x;
    int lane = tid & 31, wid = tid >> 5;
    __shared__ double gsd[CCH];
    __shared__ float xs[NN];
    __shared__ float redf[256];
    __shared__ double redd[256];
    __shared__ float sXmax, sZw;

    if (tid < CCH) {
        double s = 0.0;
        #pragma unroll
        for (int k = 0; k < KK; k++) s += (double)gt[(b * KK + k) * CCH + tid];
        gsd[tid] = (double)__fdiv_rn((float)s, 16.0f);
    }
    __syncthreads();

    for (int n = wid; n < NN; n += 8) {
        const float4* pr4 = (const float4*)(P + n * CCH);
        float4 v0 = pr4[lane];
        float4 v1 = pr4[lane + 32];
        int c0 = lane * 4, c1 = 128 + lane * 4;
        double a = 0.0;
        a = fma((double)v0.x, gsd[c0 + 0], a);
        a = fma((double)v0.y, gsd[c0 + 1], a);
        a = fma((double)v0.z, gsd[c0 + 2], a);
        a = fma((double)v0.w, gsd[c0 + 3], a);
        a = fma((double)v1.x, gsd[c1 + 0], a);
        a = fma((double)v1.y, gsd[c1 + 1], a);
        a = fma((double)v1.z, gsd[c1 + 2], a);
        a = fma((double)v1.w, gsd[c1 + 3], a);
        a = warp_sumd(a);
        if (lane == 0) xs[n] = __fdiv_rn((float)a, 0.1f);
    }
    __syncthreads();

    {
        float m = -INFINITY;
        for (int n = tid; n < NN; n += blockDim.x) m = fmaxf(m, xs[n]);
        redf[tid] = m;
        __syncthreads();
        for (int s = 128; s; s >>= 1) {
            if (tid < s) redf[tid] = fmaxf(redf[tid], redf[tid + s]);
            __syncthreads();
        }
        if (tid == 0) sXmax = redf[0];
        __syncthreads();
    }
    float X = sXmax;

    {
        double z = 0.0;
        for (int n = tid; n < NN; n += blockDim.x) {
            float e = expf(__fsub_rn(xs[n], X));
            if (e >= FMINF) z += (double)e;
        }
        redd[tid] = z;
        __syncthreads();
        for (int s = 128; s; s >>= 1) {
            if (tid < s) redd[tid] += redd[tid + s];
            __syncthreads();
        }
        if (tid == 0) sZw = (float)redd[0];
        __syncthreads();
    }
    float Zw = sZw;

    for (int n = tid; n < NN; n += blockDim.x) {
        float e = expf(__fsub_rn(xs[n], X));
        if (e < FMINF) e = 0.f;
        float w = __fdiv_rn(e, Zw);
        if (w < FMINF) w = 0.f;
        g_w[b * NN + n] = w;
    }
}

// ---------------------------------------------------------------------------
// prep: element-transpose P/Q (+ norms). Word k of each 16-word group goes to
// position (k&3)*4 + (k>>2)  =>  LDS.128 at word q*4 yields k={q,q+4,q+8,q+12}.
// ---------------------------------------------------------------------------
__global__ void prep_pz_kernel(const float* __restrict__ P) {
    int lane = threadIdx.x & 31, wid = threadIdx.x >> 5;
    int row = blockIdx.x * 8 + wid;
    const float4* p4 = (const float4*)(P + (size_t)row * CCH);
    float4 v0 = p4[lane], v1 = p4[lane + 32];
    float s = warp_sumf(dot8(v0, v1, v0, v1));
    if (lane == 0) g_pn2[row] = s;

    float* dst = g_Pz + (size_t)row * CCH;
    int b0 = (lane >> 2) * 16 + (lane & 3);
    dst[b0 + 0] = v0.x; dst[b0 + 4] = v0.y; dst[b0 + 8] = v0.z; dst[b0 + 12] = v0.w;
    int b1 = ((lane >> 2) + 8) * 16 + (lane & 3);
    dst[b1 + 0] = v1.x; dst[b1 + 4] = v1.y; dst[b1 + 8] = v1.z; dst[b1 + 12] = v1.w;
}

__global__ void prep_qz_kernel(const float* __restrict__ Q) {
    int lane = threadIdx.x & 31, wid = threadIdx.x >> 5;
    int row = blockIdx.x * 8 + wid;
    const float4* q4 = (const float4*)(Q + (size_t)row * CCH);
    float4 v0 = q4[lane], v1 = q4[lane + 32];
    float s = warp_sumf(dot8(v0, v1, v0, v1));
    if (lane == 0) g_qq[row] = s;

    float* dst = g_Qz + (size_t)row * CCH;
    int b0 = (lane >> 2) * 16 + (lane & 3);
    dst[b0 + 0] = v0.x; dst[b0 + 4] = v0.y; dst[b0 + 8] = v0.z; dst[b0 + 12] = v0.w;
    int b1 = ((lane >> 2) + 8) * 16 + (lane & 3);
    dst[b1 + 0] = v1.x; dst[b1 + 4] = v1.y; dst[b1 + 8] = v1.z; dst[b1 + 12] = v1.w;
}

// ---------------------------------------------------------------------------
// Main kernel: TF32 mma filter + exact refinement.
// Block = 32 rows x 512 protos, 256 threads (8 warps = 8 N-octants).
// 2 blocks/SM (barrier-independent) for latency overlap.
// Staging = identity LDG.128->STS.128 from pre-swizzled g_Pz/g_Qz.
// ---------------------------------------------------------------------------
struct __align__(16) SmemT {
    float p_s[NN][16];       // one k16 group, fragment-ready (32 KB)
    float q_s[32][16];       // (2 KB)
    float wS[NN], pn2S[NN];
    float dmS[8][32];
    int   cnt[32];
    int   cand_n[32][NCAND];
    float candd[32][NCAND];
};

__global__ void __launch_bounds__(256, 2)
match_kernel(const float* __restrict__ Q, const float* __restrict__ P,
             float* __restrict__ out) {
    extern __shared__ char smem_raw[];
    SmemT& S = *(SmemT*)smem_raw;

    int tid = threadIdx.x;
    int lane = tid & 31, w = tid >> 5;
    int nq = w;                       // N-octant
    int g = lane >> 2, q = lane & 3;

    int R0 = blockIdx.x * 32;
    int b = R0 >> 13;

    for (int i = tid; i < NN; i += 256) {
        S.wS[i] = g_w[b * NN + i];
        S.pn2S[i] = g_pn2[i];
    }
    if (tid < 32) { S.cnt[tid] = 1; S.cand_n[tid][0] = 0; }

    const float* Qb = Q + (size_t)R0 * CCH;

    float acc[2][8][4];
    #pragma unroll
    for (int ms = 0; ms < 2; ms++)
        #pragma unroll
        for (int ns = 0; ns < 8; ns++)
            #pragma unroll
            for (int e = 0; e < 4; e++) acc[ms][ns][e] = 0.f;

    for (int cc = 0; cc < 16; cc++) {
        __syncthreads();              // previous chunk consumed
        // stage P (identity copy, 8 x float4 per thread)
        #pragma unroll
        for (int r = 0; r < 8; r++) {
            int idx = tid + r * 256;              // 0..2047
            int n = idx >> 2, f = idx & 3;
            float4 v = *(const float4*)(g_Pz + (size_t)n * CCH + cc * 16 + f * 4);
            *(float4*)&S.p_s[n][f * 4] = v;
        }
        // stage Q (rows R0..R0+31)
        if (tid < 128) {
            int l = tid >> 2, f = tid & 3;
            float4 v = *(const float4*)(g_Qz + (size_t)(R0 + l) * CCH + cc * 16 + f * 4);
            *(float4*)&S.q_s[l][f * 4] = v;
        }
        __syncthreads();

        float4 A[2][2];
        #pragma unroll
        for (int ms = 0; ms < 2; ms++)
            #pragma unroll
            for (int h = 0; h < 2; h++) {
                int row = ms * 16 + 8 * h + g;
                A[ms][h] = *(const float4*)&S.q_s[row][q * 4];
            }
        #pragma unroll
        for (int ns = 0; ns < 8; ns++) {
            int n = nq * 64 + ns * 8 + g;
            float4 Bv = *(const float4*)&S.p_s[n][q * 4];
            #pragma unroll
            for (int ms = 0; ms < 2; ms++) {
                mma_tf32(acc[ms][ns][0], acc[ms][ns][1], acc[ms][ns][2], acc[ms][ns][3],
                         A[ms][0].x, A[ms][1].x, A[ms][0].y, A[ms][1].y, Bv.x, Bv.y);
                mma_tf32(acc[ms][ns][0], acc[ms][ns][1], acc[ms][ns][2], acc[ms][ns][3],
                         A[ms][0].z, A[ms][1].z, A[ms][0].w, A[ms][1].w, Bv.z, Bv.w);
            }
        }
    }
    __syncthreads();

    // ---- Phase 1: per-(octant,row) local max of approx dot ----
    #pragma unroll
    for (int ms = 0; ms < 2; ms++)
        #pragma unroll
        for (int h = 0; h < 2; h++) {
            int r = ms * 16 + 8 * h + g;
            float vm = -INFINITY;
            #pragma unroll
            for (int ns = 0; ns < 8; ns++)
                #pragma unroll
                for (int e = 0; e < 2; e++)
                    vm = fmaxf(vm, acc[ms][ns][2 * h + e]);
            vm = fmaxf(vm, __shfl_xor_sync(0xffffffffu, vm, 1));
            vm = fmaxf(vm, __shfl_xor_sync(0xffffffffu, vm, 2));
            if (q == 0) S.dmS[nq][r] = vm;
        }
    __syncthreads();

    // ---- Phase 2: candidate push (approx dot within 9.4 of approx max) ----
    #pragma unroll
    for (int ms = 0; ms < 2; ms++)
        #pragma unroll
        for (int h = 0; h < 2; h++) {
            int r = ms * 16 + 8 * h + g;
            float gdm = -INFINITY;
            #pragma unroll
            for (int o = 0; o < 8; o++) gdm = fmaxf(gdm, S.dmS[o][r]);
            float dthr = gdm - 9.4f;
            #pragma unroll
            for (int ns = 0; ns < 8; ns++)
                #pragma unroll
                for (int e = 0; e < 2; e++) {
                    float v = acc[ms][ns][2 * h + e];
                    int n = nq * 64 + ns * 8 + 2 * q + e;
                    if (n != 0 && v > dthr) {
                        int slot = atomicAdd(&S.cnt[r], 1);
                        if (slot < NCAND) S.cand_n[r][slot] = n;
                    }
                }
        }
    __syncthreads();

    // ---- Phase 3: owner warp refines 4 rows (exact f32; FTZ chain) ----
    #pragma unroll 1
    for (int rr = 0; rr < 4; rr++) {
        int r = w * 4 + rr;
        int cntr = S.cnt[r];
        const float4* q4 = (const float4*)(Qb + r * CCH);

        int bn = 0;
        float bp = 0.f;
        float bd;

        if (cntr <= NCAND) {
            int m = cntr;
            float4 qa = q4[lane], qb = q4[lane + 32];

            #pragma unroll 1
            for (int i0 = 0; i0 < m; i0 += 4) {
                int mm = min(4, m - i0);
                float4 pa[4], pb[4];
                #pragma unroll
                for (int j = 0; j < 4; j++)
                    if (j < mm) {
                        const float4* p4 =
                            (const float4*)(P + S.cand_n[r][i0 + j] * CCH);
                        pa[j] = p4[lane];
                        pb[j] = p4[lane + 32];
                    }
                float s[4];
                #pragma unroll
                for (int j = 0; j < 4; j++)
                    if (j < mm) s[j] = dot8(qa, qb, pa[j], pb[j]);
                #pragma unroll
                for (int o = 16; o; o >>= 1)
                    #pragma unroll
                    for (int j = 0; j < 4; j++)
                        if (j < mm) s[j] += __shfl_xor_sync(0xffffffffu, s[j], o);
                if (lane == 0)
                    #pragma unroll
                    for (int j = 0; j < 4; j++)
                        if (j < mm) S.candd[r][i0 + j] = s[j];
            }
            __syncwarp();

            float dmax = S.candd[r][0];
            for (int i = 1; i < m; i++) dmax = fmaxf(dmax, S.candd[r][i]);
            float Xf = __fdiv_rn(dmax, 0.1f);

            double z = 0.0;
            for (int i = 0; i < m; i++) {
                float x = __fdiv_rn(S.candd[r][i], 0.1f);
                float e = expf(__fsub_rn(x, Xf));
                if (e >= FMINF) z += (double)e;
            }
            float Za = (float)z;

            bd = S.candd[r][0];
            for (int i = 0; i < m; i++) {
                int n = S.cand_n[r][i];
                float d = S.candd[r][i];
                float x = __fdiv_rn(d, 0.1f);
                float e = expf(__fsub_rn(x, Xf));
                if (e < FMINF) e = 0.f;
                float sc = __fdiv_rn(e, Za);
                if (sc < FMINF) sc = 0.f;
                float p = __fmul_rn(sc, S.wS[n]);
                if (p < FMINF) p = 0.f;
                if (p > bp || (p == bp && p > 0.f && n < bn)) {
                    bp = p; bn = n; bd = d;
                }
            }
        } else {
            // overflow: full exact 512-proto scan (rare; always correct).
            // p_s is dead — column w (w<8) as per-warp dot scratch.
            #pragma unroll 1
            for (int n = 0; n < NN; n++) {
                const float4* p4 = (const float4*)(P + n * CCH);
                float s = warp_sumf(dot8(q4[lane], q4[lane + 32],
                                         p4[lane], p4[lane + 32]));
                if (lane == 0) S.p_s[n][w] = s;
            }
            __syncwarp();
            float dmax = -INFINITY;
            for (int n = 0; n < NN; n++) dmax = fmaxf(dmax, S.p_s[n][w]);
            float Xf = __fdiv_rn(dmax, 0.1f);
            double z = 0.0;
            for (int n = 0; n < NN; n++) {
                float x = __fdiv_rn(S.p_s[n][w], 0.1f);
                float e = expf(__fsub_rn(x, Xf));
                if (e >= FMINF) z += (double)e;
            }
            float Za = (float)z;
            bd = S.p_s[0][w];
            for (int n = 0; n < NN; n++) {
                float d = S.p_s[n][w];
                float x = __fdiv_rn(d, 0.1f);
                float e = expf(__fsub_rn(x, Xf));
                if (e < FMINF) e = 0.f;
                float sc = __fdiv_rn(e, Za);
                if (sc < FMINF) sc = 0.f;
                float p = __fmul_rn(sc, S.wS[n]);
                if (p < FMINF) p = 0.f;
                if (p > bp) { bp = p; bn = n; bd = d; }
            }
        }

        if (lane == 0) {
            int row = R0 + r;
            out[row] = fmaf(-2.0f, bd, g_qq[row]) + S.pn2S[bn];
        }
    }
}

// ---------------------------------------------------------------------------
extern "C" void kernel_launch(void* const* d_in, const int* in_sizes, int n_in,
                              void* d_out, int out_size) {
    const float* Q = nullptr;
    const float* P = nullptr;
    const float* G = nullptr;
    for (int i = 0; i < n_in; i++) {
        if (in_sizes[i] == BB * LL * CCH) Q = (const float*)d_in[i];
        else if (in_sizes[i] == NN * CCH) P = (const float*)d_in[i];
        else if (in_sizes[i] == BB * KK * CCH) G = (const float*)d_in[i];
    }
    float* out = (float*)d_out;

    cudaFuncSetAttribute(match_kernel,
                         cudaFuncAttributeMaxDynamicSharedMemorySize,
                         (int)sizeof(SmemT));

    prep_w_kernel<<<BB, 256>>>(P, G);
    prep_pz_kernel<<<NN / 8, 256>>>(P);
    prep_qz_kernel<<<BB * LL / 8, 256>>>(Q);
    match_kernel<<<BB * LL / 32, 256, sizeof(SmemT)>>>(Q, P, out);
}

// round 13
// speedup vs baseline: 1.0418x; 1.0418x over previous
#include <cuda_runtime.h>
#include <cuda_bf16.h>
#include <math.h>

#define BB 8
#define LL 8192
#define CCH 256
#define NN 512
#define KK 16
#define FMINF 1.17549435e-38f
#define NCAND 32

// scratch (no allocations allowed)
__device__ float g_w[BB * NN];               // FTZ proto_weights
__device__ float g_pn2[NN];                  // |p_n|^2
__device__ float g_qq[BB * LL];              // |q_l|^2
__device__ unsigned g_Pz[NN * 128];          // bf16x2, fragment-permuted P (128 u32/row)
__device__ unsigned g_Qz[BB * LL * 128];     // bf16x2, fragment-permuted Q (32MB)

__device__ __forceinline__ float warp_maxf(float v) {
    #pragma unroll
    for (int o = 16; o; o >>= 1) v = fmaxf(v, __shfl_xor_sync(0xffffffffu, v, o));
    return v;
}
__device__ __forceinline__ float warp_sumf(float v) {
    #pragma unroll
    for (int o = 16; o; o >>= 1) v += __shfl_xor_sync(0xffffffffu, v, o);
    return v;
}
__device__ __forceinline__ double warp_sumd(double v) {
    #pragma unroll
    for (int o = 16; o; o >>= 1) v += __shfl_xor_sync(0xffffffffu, v, o);
    return v;
}

// m16n8k16 bf16 mma (row.col), f32 accumulate. Filter only.
__device__ __forceinline__ void mma_bf16(float& c0, float& c1, float& c2, float& c3,
                                         unsigned a0, unsigned a1, unsigned a2,
                                         unsigned a3, unsigned b0, unsigned b1) {
    asm volatile(
        "mma.sync.aligned.m16n8k16.row.col.f32.bf16.bf16.f32 "
        "{%0,%1,%2,%3}, {%4,%5,%6,%7}, {%8,%9}, {%0,%1,%2,%3};"
        : "+f"(c0), "+f"(c1), "+f"(c2), "+f"(c3)
        : "r"(a0), "r"(a1), "r"(a2), "r"(a3), "r"(b0), "r"(b1));
}

__device__ __forceinline__ float dot8(const float4& qa, const float4& qb,
                                      const float4& pa, const float4& pb) {
    float s = 0.f;
    s = fmaf(qa.x, pa.x, s); s = fmaf(qa.y, pa.y, s);
    s = fmaf(qa.z, pa.z, s); s = fmaf(qa.w, pa.w, s);
    s = fmaf(qb.x, pb.x, s); s = fmaf(qb.y, pb.y, s);
    s = fmaf(qb.z, pb.z, s); s = fmaf(qb.w, pb.w, s);
    return s;
}

__device__ __forceinline__ unsigned packbf(float x, float y) {
    __nv_bfloat162 h = __floats2bfloat162_rn(x, y);
    return *(unsigned*)&h;
}

// ---------------------------------------------------------------------------
// prep: per-batch FTZ proto weights (unchanged semantics)
// ---------------------------------------------------------------------------
__global__ void prep_w_kernel(const float* __restrict__ P,
                              const float* __restrict__ gt) {
    int b = blockIdx.x;
    int tid = threadIdx.x;
    int lane = tid & 31, wid = tid >> 5;
    __shared__ double gsd[CCH];
    __shared__ float xs[NN];
    __shared__ float redf[256];
    __shared__ double redd[256];
    __shared__ float sXmax, sZw;

    if (tid < CCH) {
        double s = 0.0;
        #pragma unroll
        for (int k = 0; k < KK; k++) s += (double)gt[(b * KK + k) * CCH + tid];
        gsd[tid] = (double)__fdiv_rn((float)s, 16.0f);
    }
    __syncthreads();

    for (int n = wid; n < NN; n += 8) {
        const float4* pr4 = (const float4*)(P + n * CCH);
        float4 v0 = pr4[lane];
        float4 v1 = pr4[lane + 32];
        int c0 = lane * 4, c1 = 128 + lane * 4;
        double a = 0.0;
        a = fma((double)v0.x, gsd[c0 + 0], a);
        a = fma((double)v0.y, gsd[c0 + 1], a);
        a = fma((double)v0.z, gsd[c0 + 2], a);
        a = fma((double)v0.w, gsd[c0 + 3], a);
        a = fma((double)v1.x, gsd[c1 + 0], a);
        a = fma((double)v1.y, gsd[c1 + 1], a);
        a = fma((double)v1.z, gsd[c1 + 2], a);
        a = fma((double)v1.w, gsd[c1 + 3], a);
        a = warp_sumd(a);
        if (lane == 0) xs[n] = __fdiv_rn((float)a, 0.1f);
    }
    __syncthreads();

    {
        float m = -INFINITY;
        for (int n = tid; n < NN; n += blockDim.x) m = fmaxf(m, xs[n]);
        redf[tid] = m;
        __syncthreads();
        for (int s = 128; s; s >>= 1) {
            if (tid < s) redf[tid] = fmaxf(redf[tid], redf[tid + s]);
            __syncthreads();
        }
        if (tid == 0) sXmax = redf[0];
        __syncthreads();
    }
    float X = sXmax;

    {
        double z = 0.0;
        for (int n = tid; n < NN; n += blockDim.x) {
            float e = expf(__fsub_rn(xs[n], X));
            if (e >= FMINF) z += (double)e;
        }
        redd[tid] = z;
        __syncthreads();
        for (int s = 128; s; s >>= 1) {
            if (tid < s) redd[tid] += redd[tid + s];
            __syncthreads();
        }
        if (tid == 0) sZw = (float)redd[0];
        __syncthreads();
    }
    float Zw = sZw;

    for (int n = tid; n < NN; n += blockDim.x) {
        float e = expf(__fsub_rn(xs[n], X));
        if (e < FMINF) e = 0.f;
        float w = __fdiv_rn(e, Zw);
        if (w < FMINF) w = 0.f;
        g_w[b * NN + n] = w;
    }
}

// ---------------------------------------------------------------------------
// prep: bf16-convert + fragment-permute P/Q (+ norms). 128 u32 per row.
// Per 16-col group (8 u32): kpair jp -> word (jp<4) ? 2jp : 2(jp-4)+1,
// so LDS.64 at word 2q yields (kpair q, kpair q+4).
// ---------------------------------------------------------------------------
__global__ void prep_pz_kernel(const float* __restrict__ P) {
    int lane = threadIdx.x & 31, wid = threadIdx.x >> 5;
    int row = blockIdx.x * 8 + wid;
    const float4* p4 = (const float4*)(P + (size_t)row * CCH);
    float4 v0 = p4[lane], v1 = p4[lane + 32];
    float s = warp_sumf(dot8(v0, v1, v0, v1));
    if (lane == 0) g_pn2[row] = s;

    unsigned* dst = g_Pz + (size_t)row * 128;
    int gq = lane >> 2, f = lane & 3;
    int w1 = (f < 2) ? 4 * f : 4 * f - 7;
    int w2 = (f < 2) ? 4 * f + 2 : 4 * f - 5;
    dst[gq * 8 + w1] = packbf(v0.x, v0.y);
    dst[gq * 8 + w2] = packbf(v0.z, v0.w);
    dst[(gq + 8) * 8 + w1] = packbf(v1.x, v1.y);
    dst[(gq + 8) * 8 + w2] = packbf(v1.z, v1.w);
}

__global__ void prep_qz_kernel(const float* __restrict__ Q) {
    int lane = threadIdx.x & 31, wid = threadIdx.x >> 5;
    int row = blockIdx.x * 8 + wid;
    const float4* q4 = (const float4*)(Q + (size_t)row * CCH);
    float4 v0 = q4[lane], v1 = q4[lane + 32];
    float s = warp_sumf(dot8(v0, v1, v0, v1));
    if (lane == 0) g_qq[row] = s;

    unsigned* dst = g_Qz + (size_t)row * 128;
    int gq = lane >> 2, f = lane & 3;
    int w1 = (f < 2) ? 4 * f : 4 * f - 7;
    int w2 = (f < 2) ? 4 * f + 2 : 4 * f - 5;
    dst[gq * 8 + w1] = packbf(v0.x, v0.y);
    dst[gq * 8 + w2] = packbf(v0.z, v0.w);
    dst[(gq + 8) * 8 + w1] = packbf(v1.x, v1.y);
    dst[(gq + 8) * 8 + w2] = packbf(v1.z, v1.w);
}

// ---------------------------------------------------------------------------
// Main kernel: bf16 m16n8k16 filter + exact f32 refinement.
// Block = 64 rows x 512 protos, 512 threads (16 warps = 2 L-halves x 8 N-octs).
// k32 chunks (8 iters). Row stride 24 u32 => conflict-free LDS.64 fragments.
// ---------------------------------------------------------------------------
struct __align__(16) SmemT {
    unsigned p_s[NN][24];    // one k32 chunk of P (16 used + pad) ~48KB
    unsigned q_s[64][24];    // ~6KB
    float wS[NN], pn2S[NN];
    float dmS[8][64];
    int   cnt[64];
    int   cand_n[64][NCAND];
    float candd[64][NCAND];
};

__global__ void __launch_bounds__(512, 1)
match_kernel(const float* __restrict__ Q, const float* __restrict__ P,
             float* __restrict__ out) {
    extern __shared__ char smem_raw[];
    SmemT& S = *(SmemT*)smem_raw;

    int tid = threadIdx.x;
    int lane = tid & 31, w = tid >> 5;
    int lh = w & 1;                  // L half (32 rows)
    int nq = w >> 1;                 // N octant (64 protos)
    int g = lane >> 2, q = lane & 3;

    int R0 = blockIdx.x * 64;
    int b = R0 >> 13;

    if (tid < NN) {
        S.wS[tid] = g_w[b * NN + tid];
        S.pn2S[tid] = g_pn2[tid];
    }
    if (tid < 64) { S.cnt[tid] = 1; S.cand_n[tid][0] = 0; }

    const float* Qb = Q + (size_t)R0 * CCH;

    float acc[2][8][4];
    #pragma unroll
    for (int ms = 0; ms < 2; ms++)
        #pragma unroll
        for (int ns = 0; ns < 8; ns++)
            #pragma unroll
            for (int e = 0; e < 4; e++) acc[ms][ns][e] = 0.f;

    for (int cc = 0; cc < 8; cc++) {
        __syncthreads();
        // stage P chunk: thread owns row tid, 4 x uint4 (64B)
        {
            const uint4* src = (const uint4*)(g_Pz + (size_t)tid * 128 + cc * 16);
            uint4 v0 = src[0], v1 = src[1], v2 = src[2], v3 = src[3];
            *(uint4*)&S.p_s[tid][0] = v0;
            *(uint4*)&S.p_s[tid][4] = v1;
            *(uint4*)&S.p_s[tid][8] = v2;
            *(uint4*)&S.p_s[tid][12] = v3;
        }
        // stage Q chunk: 64 rows x 16 u32 = 256 uint4; threads 0..255
        if (tid < 256) {
            int l = tid >> 2, j = tid & 3;
            uint4 v = ((const uint4*)(g_Qz + (size_t)(R0 + l) * 128 + cc * 16))[j];
            *(uint4*)&S.q_s[l][j * 4] = v;
        }
        __syncthreads();

        #pragma unroll
        for (int grp = 0; grp < 2; grp++) {       // two k16 steps
            int wo = grp * 8 + 2 * q;
            uint2 A0[2], A1[2];                   // [ms]: rows g / g+8
            #pragma unroll
            for (int ms = 0; ms < 2; ms++) {
                int r0 = lh * 32 + ms * 16 + g;
                A0[ms] = *(const uint2*)&S.q_s[r0][wo];
                A1[ms] = *(const uint2*)&S.q_s[r0 + 8][wo];
            }
            #pragma unroll
            for (int ns = 0; ns < 8; ns++) {
                int n = nq * 64 + ns * 8 + g;
                uint2 Bv = *(const uint2*)&S.p_s[n][wo];
                #pragma unroll
                for (int ms = 0; ms < 2; ms++) {
                    mma_bf16(acc[ms][ns][0], acc[ms][ns][1],
                             acc[ms][ns][2], acc[ms][ns][3],
                             A0[ms].x, A1[ms].x, A0[ms].y, A1[ms].y,
                             Bv.x, Bv.y);
                }
            }
        }
    }
    __syncthreads();

    // ---- Phase 1: per-(octant,row) local max of approx dot ----
    #pragma unroll
    for (int ms = 0; ms < 2; ms++)
        #pragma unroll
        for (int h = 0; h < 2; h++) {
            int r = lh * 32 + ms * 16 + 8 * h + g;
            float vm = -INFINITY;
            #pragma unroll
            for (int ns = 0; ns < 8; ns++)
                #pragma unroll
                for (int e = 0; e < 2; e++)
                    vm = fmaxf(vm, acc[ms][ns][2 * h + e]);
            vm = fmaxf(vm, __shfl_xor_sync(0xffffffffu, vm, 1));
            vm = fmaxf(vm, __shfl_xor_sync(0xffffffffu, vm, 2));
            if (q == 0) S.dmS[nq][r] = vm;
        }
    __syncthreads();

    // ---- Phase 2: candidate push (approx dot within 9.9 of approx max;
    //      slack over FTZ cutoff 8.734 covers bf16 filter error) ----
    #pragma unroll
    for (int ms = 0; ms < 2; ms++)
        #pragma unroll
        for (int h = 0; h < 2; h++) {
            int r = lh * 32 + ms * 16 + 8 * h + g;
            float gdm = -INFINITY;
            #pragma unroll
            for (int o = 0; o < 8; o++) gdm = fmaxf(gdm, S.dmS[o][r]);
            float dthr = gdm - 9.9f;
            #pragma unroll
            for (int ns = 0; ns < 8; ns++)
                #pragma unroll
                for (int e = 0; e < 2; e++) {
                    float v = acc[ms][ns][2 * h + e];
                    int n = nq * 64 + ns * 8 + 2 * q + e;
                    if (n != 0 && v > dthr) {
                        int slot = atomicAdd(&S.cnt[r], 1);
                        if (slot < NCAND) S.cand_n[r][slot] = n;
                    }
                }
        }
    __syncthreads();

    // ---- Phase 3: owner warp refines 4 rows (exact f32; FTZ chain) ----
    #pragma unroll 1
    for (int rr = 0; rr < 4; rr++) {
        int r = w * 4 + rr;
        int cntr = S.cnt[r];
        const float4* q4 = (const float4*)(Qb + r * CCH);

        int bn = 0;
        float bp = 0.f;
        float bd;

        if (cntr <= NCAND) {
            int m = cntr;
            float4 qa = q4[lane], qb = q4[lane + 32];

            #pragma unroll 1
            for (int i0 = 0; i0 < m; i0 += 4) {
                int mm = min(4, m - i0);
                float4 pa[4], pb[4];
                #pragma unroll
                for (int j = 0; j < 4; j++)
                    if (j < mm) {
                        const float4* p4 =
                            (const float4*)(P + S.cand_n[r][i0 + j] * CCH);
                        pa[j] = p4[lane];
                        pb[j] = p4[lane + 32];
                    }
                float s[4];
                #pragma unroll
                for (int j = 0; j < 4; j++)
                    if (j < mm) s[j] = dot8(qa, qb, pa[j], pb[j]);
                #pragma unroll
                for (int o = 16; o; o >>= 1)
                    #pragma unroll
                    for (int j = 0; j < 4; j++)
                        if (j < mm) s[j] += __shfl_xor_sync(0xffffffffu, s[j], o);
                if (lane == 0)
                    #pragma unroll
                    for (int j = 0; j < 4; j++)
                        if (j < mm) S.candd[r][i0 + j] = s[j];
            }
            __syncwarp();

            float dmax = S.candd[r][0];
            for (int i = 1; i < m; i++) dmax = fmaxf(dmax, S.candd[r][i]);
            float Xf = __fdiv_rn(dmax, 0.1f);

            double z = 0.0;
            for (int i = 0; i < m; i++) {
                float x = __fdiv_rn(S.candd[r][i], 0.1f);
                float e = expf(__fsub_rn(x, Xf));
                if (e >= FMINF) z += (double)e;
            }
            float Za = (float)z;

            bd = S.candd[r][0];
            for (int i = 0; i < m; i++) {
                int n = S.cand_n[r][i];
                float d = S.candd[r][i];
                float x = __fdiv_rn(d, 0.1f);
                float e = expf(__fsub_rn(x, Xf));
                if (e < FMINF) e = 0.f;
                float sc = __fdiv_rn(e, Za);
                if (sc < FMINF) sc = 0.f;
                float p = __fmul_rn(sc, S.wS[n]);
                if (p < FMINF) p = 0.f;
                if (p > bp || (p == bp && p > 0.f && n < bn)) {
                    bp = p; bn = n; bd = d;
                }
            }
        } else {
            // overflow: full exact 512-proto scan (rare; always correct).
            // p_s is dead — word w (w<16) of each row as per-warp scratch.
            #pragma unroll 1
            for (int n = 0; n < NN; n++) {
                const float4* p4 = (const float4*)(P + n * CCH);
                float s = warp_sumf(dot8(q4[lane], q4[lane + 32],
                                         p4[lane], p4[lane + 32]));
                if (lane == 0) S.p_s[n][w] = __float_as_uint(s);
            }
            __syncwarp();
            float dmax = -INFINITY;
            for (int n = 0; n < NN; n++)
                dmax = fmaxf(dmax, __uint_as_float(S.p_s[n][w]));
            float Xf = __fdiv_rn(dmax, 0.1f);
            double z = 0.0;
            for (int n = 0; n < NN; n++) {
                float x = __fdiv_rn(__uint_as_float(S.p_s[n][w]), 0.1f);
                float e = expf(__fsub_rn(x, Xf));
                if (e >= FMINF) z += (double)e;
            }
            float Za = (float)z;
            bd = __uint_as_float(S.p_s[0][w]);
            for (int n = 0; n < NN; n++) {
                float d = __uint_as_float(S.p_s[n][w]);
                float x = __fdiv_rn(d, 0.1f);
                float e = expf(__fsub_rn(x, Xf));
                if (e < FMINF) e = 0.f;
                float sc = __fdiv_rn(e, Za);
                if (sc < FMINF) sc = 0.f;
                float p = __fmul_rn(sc, S.wS[n]);
                if (p < FMINF) p = 0.f;
                if (p > bp) { bp = p; bn = n; bd = d; }
            }
        }

        if (lane == 0) {
            int row = R0 + r;
            out[row] = fmaf(-2.0f, bd, g_qq[row]) + S.pn2S[bn];
        }
    }
}

// ---------------------------------------------------------------------------
extern "C" void kernel_launch(void* const* d_in, const int* in_sizes, int n_in,
                              void* d_out, int out_size) {
    const float* Q = nullptr;
    const float* P = nullptr;
    const float* G = nullptr;
    for (int i = 0; i < n_in; i++) {
        if (in_sizes[i] == BB * LL * CCH) Q = (const float*)d_in[i];
        else if (in_sizes[i] == NN * CCH) P = (const float*)d_in[i];
        else if (in_sizes[i] == BB * KK * CCH) G = (const float*)d_in[i];
    }
    float* out = (float*)d_out;

    cudaFuncSetAttribute(match_kernel,
                         cudaFuncAttributeMaxDynamicSharedMemorySize,
                         (int)sizeof(SmemT));

    prep_w_kernel<<<BB, 256>>>(P, G);
    prep_pz_kernel<<<NN / 8, 256>>>(P);
    prep_qz_kernel<<<BB * LL / 8, 256>>>(Q);
    match_kernel<<<BB * LL / 64, 512, sizeof(SmemT)>>>(Q, P, out);
}

// round 14
// speedup vs baseline: 1.1640x; 1.1173x over previous
#include <cuda_runtime.h>
#include <cuda_bf16.h>
#include <math.h>

#define BB 8
#define LL 8192
#define CCH 256
#define NN 512
#define KK 16
#define FMINF 1.17549435e-38f
#define NCAND 32

// scratch (no allocations allowed)
__device__ float g_w[BB * NN];               // FTZ proto_weights
__device__ float g_pn2[NN];                  // |p_n|^2
__device__ float g_qq[BB * LL];              // |q_l|^2
__device__ unsigned g_Pz[NN * 128];          // bf16x2, fragment-permuted P (128 u32/row)
__device__ unsigned g_Qz[BB * LL * 128];     // bf16x2, fragment-permuted Q (32MB)

__device__ __forceinline__ float warp_maxf(float v) {
    #pragma unroll
    for (int o = 16; o; o >>= 1) v = fmaxf(v, __shfl_xor_sync(0xffffffffu, v, o));
    return v;
}
__device__ __forceinline__ float warp_sumf(float v) {
    #pragma unroll
    for (int o = 16; o; o >>= 1) v += __shfl_xor_sync(0xffffffffu, v, o);
    return v;
}
__device__ __forceinline__ double warp_sumd(double v) {
    #pragma unroll
    for (int o = 16; o; o >>= 1) v += __shfl_xor_sync(0xffffffffu, v, o);
    return v;
}

// m16n8k16 bf16 mma (row.col), f32 accumulate. Filter only.
__device__ __forceinline__ void mma_bf16(float& c0, float& c1, float& c2, float& c3,
                                         unsigned a0, unsigned a1, unsigned a2,
                                         unsigned a3, unsigned b0, unsigned b1) {
    asm volatile(
        "mma.sync.aligned.m16n8k16.row.col.f32.bf16.bf16.f32 "
        "{%0,%1,%2,%3}, {%4,%5,%6,%7}, {%8,%9}, {%0,%1,%2,%3};"
        : "+f"(c0), "+f"(c1), "+f"(c2), "+f"(c3)
        : "r"(a0), "r"(a1), "r"(a2), "r"(a3), "r"(b0), "r"(b1));
}

__device__ __forceinline__ float dot8(const float4& qa, const float4& qb,
                                      const float4& pa, const float4& pb) {
    float s = 0.f;
    s = fmaf(qa.x, pa.x, s); s = fmaf(qa.y, pa.y, s);
    s = fmaf(qa.z, pa.z, s); s = fmaf(qa.w, pa.w, s);
    s = fmaf(qb.x, pb.x, s); s = fmaf(qb.y, pb.y, s);
    s = fmaf(qb.z, pb.z, s); s = fmaf(qb.w, pb.w, s);
    return s;
}

__device__ __forceinline__ unsigned packbf(float x, float y) {
    __nv_bfloat162 h = __floats2bfloat162_rn(x, y);
    return *(unsigned*)&h;
}

// ---------------------------------------------------------------------------
// prep: per-batch FTZ proto weights (unchanged semantics)
// ---------------------------------------------------------------------------
__global__ void prep_w_kernel(const float* __restrict__ P,
                              const float* __restrict__ gt) {
    int b = blockIdx.x;
    int tid = threadIdx.x;
    int lane = tid & 31, wid = tid >> 5;
    __shared__ double gsd[CCH];
    __shared__ float xs[NN];
    __shared__ float redf[256];
    __shared__ double redd[256];
    __shared__ float sXmax, sZw;

    if (tid < CCH) {
        double s = 0.0;
        #pragma unroll
        for (int k = 0; k < KK; k++) s += (double)gt[(b * KK + k) * CCH + tid];
        gsd[tid] = (double)__fdiv_rn((float)s, 16.0f);
    }
    __syncthreads();

    for (int n = wid; n < NN; n += 8) {
        const float4* pr4 = (const float4*)(P + n * CCH);
        float4 v0 = pr4[lane];
        float4 v1 = pr4[lane + 32];
        int c0 = lane * 4, c1 = 128 + lane * 4;
        double a = 0.0;
        a = fma((double)v0.x, gsd[c0 + 0], a);
        a = fma((double)v0.y, gsd[c0 + 1], a);
        a = fma((double)v0.z, gsd[c0 + 2], a);
        a = fma((double)v0.w, gsd[c0 + 3], a);
        a = fma((double)v1.x, gsd[c1 + 0], a);
        a = fma((double)v1.y, gsd[c1 + 1], a);
        a = fma((double)v1.z, gsd[c1 + 2], a);
        a = fma((double)v1.w, gsd[c1 + 3], a);
        a = warp_sumd(a);
        if (lane == 0) xs[n] = __fdiv_rn((float)a, 0.1f);
    }
    __syncthreads();

    {
        float m = -INFINITY;
        for (int n = tid; n < NN; n += blockDim.x) m = fmaxf(m, xs[n]);
        redf[tid] = m;
        __syncthreads();
        for (int s = 128; s; s >>= 1) {
            if (tid < s) redf[tid] = fmaxf(redf[tid], redf[tid + s]);
            __syncthreads();
        }
        if (tid == 0) sXmax = redf[0];
        __syncthreads();
    }
    float X = sXmax;

    {
        double z = 0.0;
        for (int n = tid; n < NN; n += blockDim.x) {
            float e = expf(__fsub_rn(xs[n], X));
            if (e >= FMINF) z += (double)e;
        }
        redd[tid] = z;
        __syncthreads();
        for (int s = 128; s; s >>= 1) {
            if (tid < s) redd[tid] += redd[tid + s];
            __syncthreads();
        }
        if (tid == 0) sZw = (float)redd[0];
        __syncthreads();
    }
    float Zw = sZw;

    for (int n = tid; n < NN; n += blockDim.x) {
        float e = expf(__fsub_rn(xs[n], X));
        if (e < FMINF) e = 0.f;
        float w = __fdiv_rn(e, Zw);
        if (w < FMINF) w = 0.f;
        g_w[b * NN + n] = w;
    }
}

// ---------------------------------------------------------------------------
// prep: bf16-convert + fragment-permute P/Q (+ norms). 128 u32 per row.
// Per 16-col group (8 u32): kpair jp -> word (jp<4) ? 2jp : 2(jp-4)+1,
// so an 8B load at word 2q yields (kpair q, kpair q+4).
// ---------------------------------------------------------------------------
__global__ void prep_pz_kernel(const float* __restrict__ P) {
    int lane = threadIdx.x & 31, wid = threadIdx.x >> 5;
    int row = blockIdx.x * 8 + wid;
    const float4* p4 = (const float4*)(P + (size_t)row * CCH);
    float4 v0 = p4[lane], v1 = p4[lane + 32];
    float s = warp_sumf(dot8(v0, v1, v0, v1));
    if (lane == 0) g_pn2[row] = s;

    unsigned* dst = g_Pz + (size_t)row * 128;
    int gq = lane >> 2, f = lane & 3;
    int w1 = (f < 2) ? 4 * f : 4 * f - 7;
    int w2 = (f < 2) ? 4 * f + 2 : 4 * f - 5;
    dst[gq * 8 + w1] = packbf(v0.x, v0.y);
    dst[gq * 8 + w2] = packbf(v0.z, v0.w);
    dst[(gq + 8) * 8 + w1] = packbf(v1.x, v1.y);
    dst[(gq + 8) * 8 + w2] = packbf(v1.z, v1.w);
}

__global__ void prep_qz_kernel(const float* __restrict__ Q) {
    int lane = threadIdx.x & 31, wid = threadIdx.x >> 5;
    int row = blockIdx.x * 8 + wid;
    const float4* q4 = (const float4*)(Q + (size_t)row * CCH);
    float4 v0 = q4[lane], v1 = q4[lane + 32];
    float s = warp_sumf(dot8(v0, v1, v0, v1));
    if (lane == 0) g_qq[row] = s;

    unsigned* dst = g_Qz + (size_t)row * 128;
    int gq = lane >> 2, f = lane & 3;
    int w1 = (f < 2) ? 4 * f : 4 * f - 7;
    int w2 = (f < 2) ? 4 * f + 2 : 4 * f - 5;
    dst[gq * 8 + w1] = packbf(v0.x, v0.y);
    dst[gq * 8 + w2] = packbf(v0.z, v0.w);
    dst[(gq + 8) * 8 + w1] = packbf(v1.x, v1.y);
    dst[(gq + 8) * 8 + w2] = packbf(v1.z, v1.w);
}

// ---------------------------------------------------------------------------
// Main kernel: bf16 m16n8k16 filter + exact f32 refinement.
// Block = 64 rows x 512 protos, 512 threads (16 warps = 2 L-halves x 8 N-octs).
// Q tile staged to smem ONCE (one barrier); B operands via LDG.64 from
// L2-resident g_Pz. Mainloop has ZERO barriers — warps free-run.
// Smem Q row stride 136 (== 8 mod 32) => 2-phase conflict-free LDS.64.
// ---------------------------------------------------------------------------
struct __align__(16) SmemT {
    unsigned q_s[64][136];   // full bf16 Q tile, padded (34.8 KB)
    float wS[NN], pn2S[NN];
    float dmS[8][64];
    int   cnt[64];
    int   cand_n[64][NCAND];
    float candd[64][NCAND];
};

__global__ void __launch_bounds__(512, 1)
match_kernel(const float* __restrict__ Q, const float* __restrict__ P,
             float* __restrict__ out) {
    extern __shared__ char smem_raw[];
    SmemT& S = *(SmemT*)smem_raw;

    int tid = threadIdx.x;
    int lane = tid & 31, w = tid >> 5;
    int lh = w & 1;                  // L half (32 rows)
    int nq = w >> 1;                 // N octant (64 protos)
    int g = lane >> 2, q = lane & 3;

    int R0 = blockIdx.x * 64;
    int b = R0 >> 13;

    if (tid < NN) {
        S.wS[tid] = g_w[b * NN + tid];
        S.pn2S[tid] = g_pn2[tid];
    }
    if (tid < 64) { S.cnt[tid] = 1; S.cand_n[tid][0] = 0; }

    // stage the full Q tile once: 64 rows x 128 u32 = 2048 uint4
    #pragma unroll
    for (int r = 0; r < 4; r++) {
        int idx = tid + r * 512;             // 0..2047
        int l = idx >> 5, j = idx & 31;      // row, uint4-within-row
        uint4 v = ((const uint4*)(g_Qz + (size_t)(R0 + l) * 128))[j];
        *(uint4*)&S.q_s[l][j * 4] = v;
    }
    __syncthreads();                          // the ONLY mainloop barrier

    const float* Qb = Q + (size_t)R0 * CCH;

    float acc[2][8][4];
    #pragma unroll
    for (int ms = 0; ms < 2; ms++)
        #pragma unroll
        for (int ns = 0; ns < 8; ns++)
            #pragma unroll
            for (int e = 0; e < 4; e++) acc[ms][ns][e] = 0.f;

    const unsigned* Pz = g_Pz;

    #pragma unroll 1
    for (int cc = 0; cc < 8; cc++) {
        #pragma unroll
        for (int grp = 0; grp < 2; grp++) {
            int wo = cc * 16 + grp * 8 + 2 * q;
            // B fragments: 8 independent LDG.64 (MLP=8), L2-resident
            uint2 Bv[8];
            #pragma unroll
            for (int ns = 0; ns < 8; ns++) {
                int n = nq * 64 + ns * 8 + g;
                Bv[ns] = __ldg((const uint2*)(Pz + (size_t)n * 128 + wo));
            }
            // A fragments from smem (conflict-free)
            uint2 A0[2], A1[2];
            #pragma unroll
            for (int ms = 0; ms < 2; ms++) {
                int r0 = lh * 32 + ms * 16 + g;
                A0[ms] = *(const uint2*)&S.q_s[r0][wo];
                A1[ms] = *(const uint2*)&S.q_s[r0 + 8][wo];
            }
            #pragma unroll
            for (int ns = 0; ns < 8; ns++)
                #pragma unroll
                for (int ms = 0; ms < 2; ms++)
                    mma_bf16(acc[ms][ns][0], acc[ms][ns][1],
                             acc[ms][ns][2], acc[ms][ns][3],
                             A0[ms].x, A1[ms].x, A0[ms].y, A1[ms].y,
                             Bv[ns].x, Bv[ns].y);
        }
    }
    __syncthreads();

    // ---- Phase 1: per-(octant,row) local max of approx dot ----
    #pragma unroll
    for (int ms = 0; ms < 2; ms++)
        #pragma unroll
        for (int h = 0; h < 2; h++) {
            int r = lh * 32 + ms * 16 + 8 * h + g;
            float vm = -INFINITY;
            #pragma unroll
            for (int ns = 0; ns < 8; ns++)
                #pragma unroll
                for (int e = 0; e < 2; e++)
                    vm = fmaxf(vm, acc[ms][ns][2 * h + e]);
            vm = fmaxf(vm, __shfl_xor_sync(0xffffffffu, vm, 1));
            vm = fmaxf(vm, __shfl_xor_sync(0xffffffffu, vm, 2));
            if (q == 0) S.dmS[nq][r] = vm;
        }
    __syncthreads();

    // ---- Phase 2: candidate push (approx dot within 9.9 of approx max;
    //      slack over FTZ cutoff 8.734 covers bf16 filter error) ----
    #pragma unroll
    for (int ms = 0; ms < 2; ms++)
        #pragma unroll
        for (int h = 0; h < 2; h++) {
            int r = lh * 32 + ms * 16 + 8 * h + g;
            float gdm = -INFINITY;
            #pragma unroll
            for (int o = 0; o < 8; o++) gdm = fmaxf(gdm, S.dmS[o][r]);
            float dthr = gdm - 9.9f;
            #pragma unroll
            for (int ns = 0; ns < 8; ns++)
                #pragma unroll
                for (int e = 0; e < 2; e++) {
                    float v = acc[ms][ns][2 * h + e];
                    int n = nq * 64 + ns * 8 + 2 * q + e;
                    if (n != 0 && v > dthr) {
                        int slot = atomicAdd(&S.cnt[r], 1);
                        if (slot < NCAND) S.cand_n[r][slot] = n;
                    }
                }
        }
    __syncthreads();

    // ---- Phase 3: owner warp refines 4 rows (exact f32; FTZ chain) ----
    unsigned* scr = &S.q_s[0][0];     // q_s is dead; 8704 u32 >= 512*16 scratch
    #pragma unroll 1
    for (int rr = 0; rr < 4; rr++) {
        int r = w * 4 + rr;
        int cntr = S.cnt[r];
        const float4* q4 = (const float4*)(Qb + r * CCH);

        int bn = 0;
        float bp = 0.f;
        float bd;

        if (cntr <= NCAND) {
            int m = cntr;
            float4 qa = q4[lane], qb = q4[lane + 32];

            #pragma unroll 1
            for (int i0 = 0; i0 < m; i0 += 4) {
                int mm = min(4, m - i0);
                float4 pa[4], pb[4];
                #pragma unroll
                for (int j = 0; j < 4; j++)
                    if (j < mm) {
                        const float4* p4 =
                            (const float4*)(P + S.cand_n[r][i0 + j] * CCH);
                        pa[j] = p4[lane];
                        pb[j] = p4[lane + 32];
                    }
                float s[4];
                #pragma unroll
                for (int j = 0; j < 4; j++)
                    if (j < mm) s[j] = dot8(qa, qb, pa[j], pb[j]);
                #pragma unroll
                for (int o = 16; o; o >>= 1)
                    #pragma unroll
                    for (int j = 0; j < 4; j++)
                        if (j < mm) s[j] += __shfl_xor_sync(0xffffffffu, s[j], o);
                if (lane == 0)
                    #pragma unroll
                    for (int j = 0; j < 4; j++)
                        if (j < mm) S.candd[r][i0 + j] = s[j];
            }
            __syncwarp();

            float dmax = S.candd[r][0];
            for (int i = 1; i < m; i++) dmax = fmaxf(dmax, S.candd[r][i]);
            float Xf = __fdiv_rn(dmax, 0.1f);

            double z = 0.0;
            for (int i = 0; i < m; i++) {
                float x = __fdiv_rn(S.candd[r][i], 0.1f);
                float e = expf(__fsub_rn(x, Xf));
                if (e >= FMINF) z += (double)e;
            }
            float Za = (float)z;

            bd = S.candd[r][0];
            for (int i = 0; i < m; i++) {
                int n = S.cand_n[r][i];
                float d = S.candd[r][i];
                float x = __fdiv_rn(d, 0.1f);
                float e = expf(__fsub_rn(x, Xf));
                if (e < FMINF) e = 0.f;
                float sc = __fdiv_rn(e, Za);
                if (sc < FMINF) sc = 0.f;
                float p = __fmul_rn(sc, S.wS[n]);
                if (p < FMINF) p = 0.f;
                if (p > bp || (p == bp && p > 0.f && n < bn)) {
                    bp = p; bn = n; bd = d;
                }
            }
        } else {
            // overflow: full exact 512-proto scan (rare; always correct).
            #pragma unroll 1
            for (int n = 0; n < NN; n++) {
                const float4* p4 = (const float4*)(P + n * CCH);
                float s = warp_sumf(dot8(q4[lane], q4[lane + 32],
                                         p4[lane], p4[lane + 32]));
                if (lane == 0) scr[n * 16 + w] = __float_as_uint(s);
            }
            __syncwarp();
            float dmax = -INFINITY;
            for (int n = 0; n < NN; n++)
                dmax = fmaxf(dmax, __uint_as_float(scr[n * 16 + w]));
            float Xf = __fdiv_rn(dmax, 0.1f);
            double z = 0.0;
            for (int n = 0; n < NN; n++) {
                float x = __fdiv_rn(__uint_as_float(scr[n * 16 + w]), 0.1f);
                float e = expf(__fsub_rn(x, Xf));
                if (e >= FMINF) z += (double)e;
            }
            float Za = (float)z;
            bd = __uint_as_float(scr[0 * 16 + w]);
            for (int n = 0; n < NN; n++) {
                float d = __uint_as_float(scr[n * 16 + w]);
                float x = __fdiv_rn(d, 0.1f);
                float e = expf(__fsub_rn(x, Xf));
                if (e < FMINF) e = 0.f;
                float sc = __fdiv_rn(e, Za);
                if (sc < FMINF) sc = 0.f;
                float p = __fmul_rn(sc, S.wS[n]);
                if (p < FMINF) p = 0.f;
                if (p > bp) { bp = p; bn = n; bd = d; }
            }
        }

        if (lane == 0) {
            int row = R0 + r;
            out[row] = fmaf(-2.0f, bd, g_qq[row]) + S.pn2S[bn];
        }
    }
}

// ---------------------------------------------------------------------------
extern "C" void kernel_launch(void* const* d_in, const int* in_sizes, int n_in,
                              void* d_out, int out_size) {
    const float* Q = nullptr;
    const float* P = nullptr;
    const float* G = nullptr;
    for (int i = 0; i < n_in; i++) {
        if (in_sizes[i] == BB * LL * CCH) Q = (const float*)d_in[i];
        else if (in_sizes[i] == NN * CCH) P = (const float*)d_in[i];
        else if (in_sizes[i] == BB * KK * CCH) G = (const float*)d_in[i];
    }
    float* out = (float*)d_out;

    cudaFuncSetAttribute(match_kernel,
                         cudaFuncAttributeMaxDynamicSharedMemorySize,
                         (int)sizeof(SmemT));

    prep_w_kernel<<<BB, 256>>>(P, G);
    prep_pz_kernel<<<NN / 8, 256>>>(P);
    prep_qz_kernel<<<BB * LL / 8, 256>>>(Q);
    match_kernel<<<BB * LL / 64, 512, sizeof(SmemT)>>>(Q, P, out);
}